// round 7
// baseline (speedup 1.0000x reference)
#include <cuda_runtime.h>

#define BB 8
#define SS 2048
#define HH 1024
#define NT (BB * SS)   // 16384 tokens

// Scratch (device globals — no allocation allowed in kernel_launch)
__device__ float g_ss[NT];      // score_s per token
__device__ float g_se[NT];      // score_e per token (+ bm folded in)
__device__ int   g_fl[NT];      // bit0 = start_cand, bit1 = end_cand

// Side stream + events, created at load time (global ctor precedes the
// harness's memory checkpoint; nothing is created during capture/launch).
namespace pipe {
    struct Res {
        cudaStream_t s2 = nullptr;
        cudaEvent_t  evb[BB] = {};
        cudaEvent_t  evj = nullptr;
        bool ok = false;
        Res() {
            ok = (cudaStreamCreateWithFlags(&s2, cudaStreamNonBlocking) == cudaSuccess);
            for (int b = 0; b < BB && ok; b++)
                ok = (cudaEventCreateWithFlags(&evb[b], cudaEventDisableTiming) == cudaSuccess);
            if (ok)
                ok = (cudaEventCreateWithFlags(&evj, cudaEventDisableTiming) == cudaSuccess);
        }
    };
    static Res res;   // constructed before main()
}

// ---------------------------------------------------------------------------
// Kernel 1 (per batch): 512 threads = 16 warps = 16 tokens/block, 128 blocks.
// Weights folded into smem per block (L2-hit). 1 token per warp:
// 1 streaming LDG.128 + 4 LDS.128 per 512B of rep. ~2.2us per batch.
// ---------------------------------------------------------------------------
__global__ void __launch_bounds__(512)
logits_kernel(const float* __restrict__ rep,
              const int*   __restrict__ mask,
              const float* __restrict__ Ws,  const float* __restrict__ bs,
              const float* __restrict__ We,  const float* __restrict__ be,
              const float* __restrict__ Wm,  const float* __restrict__ bm,
              int tbase)
{
    __shared__ float s_wds[HH];   // Ws[:,1]-Ws[:,0]
    __shared__ float s_wss[HH];   // Wm0*Ws[:,0]+Wm1*Ws[:,1]
    __shared__ float s_wde[HH];   // We[:,1]-We[:,0]
    __shared__ float s_wse[HH];   // Wm2*We[:,0]+Wm3*We[:,1]
    __shared__ float s_bias[4];

    const int tid = threadIdx.x;
    {
        const float wm0 = Wm[0], wm1 = Wm[1], wm2 = Wm[2], wm3 = Wm[3];
        #pragma unroll
        for (int p = 0; p < HH / 512; p++) {
            int h = p * 512 + tid;
            float a0 = Ws[2 * h], a1 = Ws[2 * h + 1];
            float c0 = We[2 * h], c1 = We[2 * h + 1];
            s_wds[h] = a1 - a0;
            s_wss[h] = wm0 * a0 + wm1 * a1;
            s_wde[h] = c1 - c0;
            s_wse[h] = wm2 * c0 + wm3 * c1;
        }
        if (tid == 0) {
            s_bias[0] = bs[1] - bs[0];
            s_bias[1] = wm0 * bs[0] + wm1 * bs[1];
            s_bias[2] = be[1] - be[0];
            s_bias[3] = wm2 * be[0] + wm3 * be[1] + bm[0];
        }
    }
    __syncthreads();

    const int t    = tbase + blockIdx.x * 16 + (tid >> 5);   // token id
    const int lane = tid & 31;

    const float4* r4  = reinterpret_cast<const float4*>(rep + (size_t)t * HH);
    const float4* wds = reinterpret_cast<const float4*>(s_wds);
    const float4* wss = reinterpret_cast<const float4*>(s_wss);
    const float4* wde = reinterpret_cast<const float4*>(s_wde);
    const float4* wse = reinterpret_cast<const float4*>(s_wse);

    float ds = 0.f, sv = 0.f, de = 0.f, se = 0.f;
    #pragma unroll
    for (int k = 0; k < HH / 128; k++) {
        int idx = k * 32 + lane;
        float4 r = __ldcs(&r4[idx]);         // streaming: rep is read-once
        float4 a = wds[idx];
        float4 b = wss[idx];
        float4 c = wde[idx];
        float4 d = wse[idx];
        ds += r.x*a.x + r.y*a.y + r.z*a.z + r.w*a.w;
        sv += r.x*b.x + r.y*b.y + r.z*b.z + r.w*b.w;
        de += r.x*c.x + r.y*c.y + r.z*c.z + r.w*c.w;
        se += r.x*d.x + r.y*d.y + r.z*d.z + r.w*d.w;
    }
    #pragma unroll
    for (int off = 16; off; off >>= 1) {
        ds += __shfl_xor_sync(0xffffffffu, ds, off);
        sv += __shfl_xor_sync(0xffffffffu, sv, off);
        de += __shfl_xor_sync(0xffffffffu, de, off);
        se += __shfl_xor_sync(0xffffffffu, se, off);
    }
    if (lane == 0) {
        int m  = (mask[t] != 0);
        int sc = m && ((ds + s_bias[0]) >= 0.f);   // s0 <= s1
        int ec = m && ((de + s_bias[2]) >= 0.f);   // e0 <= e1
        g_ss[t] = sv + s_bias[1];
        g_se[t] = se + s_bias[3];
        g_fl[t] = sc | (ec << 1);
    }
}

// ---------------------------------------------------------------------------
// Kernel 2 (per batch): one block per row i; 512 threads x float4 = 2048 cols.
// HBM-write bound (~32MB per batch). Streaming stores.
// ---------------------------------------------------------------------------
__global__ void __launch_bounds__(512)
pair_kernel(float* __restrict__ out_valid,
            float* __restrict__ out_masked,
            int b)
{
    const int i = blockIdx.x;
    const int t = b * SS + i;

    const float ss = g_ss[t];
    const bool  sc = (g_fl[t] & 1);

    const size_t rowoff = ((size_t)b * SS + i) * SS;
    float4* ov = reinterpret_cast<float4*>(out_valid  + rowoff);
    float4* om = reinterpret_cast<float4*>(out_masked + rowoff);

    const int j4 = threadIdx.x;        // one float4 (4 j's) per thread
    const int j0 = j4 * 4;

    float4 v, m;
    if (!sc || (j0 + 3) < i) {
        v = make_float4(0.f, 0.f, 0.f, 0.f);
        m = v;
    } else {
        const float4 se4 = reinterpret_cast<const float4*>(g_se + b * SS)[j4];
        const int4   fl4 = reinterpret_cast<const int4*>(g_fl + b * SS)[j4];

        float ps; bool val;
        ps = ss + se4.x; val = (fl4.x & 2) && (i <= j0 + 0) && (ps > 0.f);
        v.x = val ? 1.f : 0.f; m.x = val ? ps : 0.f;
        ps = ss + se4.y; val = (fl4.y & 2) && (i <= j0 + 1) && (ps > 0.f);
        v.y = val ? 1.f : 0.f; m.y = val ? ps : 0.f;
        ps = ss + se4.z; val = (fl4.z & 2) && (i <= j0 + 2) && (ps > 0.f);
        v.z = val ? 1.f : 0.f; m.z = val ? ps : 0.f;
        ps = ss + se4.w; val = (fl4.w & 2) && (i <= j0 + 3) && (ps > 0.f);
        v.w = val ? 1.f : 0.f; m.w = val ? ps : 0.f;
    }
    __stcs(ov + j4, v);
    __stcs(om + j4, m);
}

extern "C" void kernel_launch(void* const* d_in, const int* in_sizes, int n_in,
                              void* d_out, int out_size)
{
    const float* rep  = (const float*)d_in[0];
    const int*   mask = (const int*)  d_in[1];
    const float* Ws   = (const float*)d_in[2];
    const float* bs   = (const float*)d_in[3];
    const float* We   = (const float*)d_in[4];
    const float* be   = (const float*)d_in[5];
    const float* Wm   = (const float*)d_in[6];
    const float* bm   = (const float*)d_in[7];

    float* out = (float*)d_out;
    const size_t half = (size_t)BB * SS * SS;   // valid first, masked second

    if (pipe::res.ok) {
        // Pipelined: logits batches on default stream; pair_b on side stream
        // overlaps logits_{b+1..}. Fork/join via events (graph-capture safe).
        for (int b = 0; b < BB; b++) {
            logits_kernel<<<SS / 16, 512>>>(rep, mask, Ws, bs, We, be, Wm, bm,
                                            b * SS);
            cudaEventRecord(pipe::res.evb[b], 0);
            cudaStreamWaitEvent(pipe::res.s2, pipe::res.evb[b], 0);
            pair_kernel<<<SS, 512, 0, pipe::res.s2>>>(out, out + half, b);
        }
        cudaEventRecord(pipe::res.evj, pipe::res.s2);
        cudaStreamWaitEvent(0, pipe::res.evj, 0);
    } else {
        // Fallback: sequential on default stream.
        for (int b = 0; b < BB; b++)
            logits_kernel<<<SS / 16, 512>>>(rep, mask, Ws, bs, We, be, Wm, bm,
                                            b * SS);
        for (int b = 0; b < BB; b++)
            pair_kernel<<<SS, 512>>>(out, out + half, b);
    }
}

// round 8
// speedup vs baseline: 1.5757x; 1.5757x over previous
#include <cuda_runtime.h>

#define BB 8
#define SS 2048
#define HH 1024
#define NT (BB * SS)   // 16384 tokens
#define HB (BB / 2)    // batches per half

// Scratch (device globals — no allocation allowed in kernel_launch)
__device__ float g_ss[NT];      // score_s per token
__device__ float g_se[NT];      // score_e per token (+ bm folded in)
__device__ int   g_fl[NT];      // bit0 = start_cand, bit1 = end_cand

// Side stream + events, created at load time (global ctor precedes the
// harness's memory checkpoint; nothing is created during capture/launch).
namespace pipe {
    struct Res {
        cudaStream_t s2 = nullptr;
        cudaEvent_t  ev0 = nullptr, ev1 = nullptr, evj = nullptr;
        bool ok = false;
        Res() {
            ok = (cudaStreamCreateWithFlags(&s2, cudaStreamNonBlocking) == cudaSuccess)
              && (cudaEventCreateWithFlags(&ev0, cudaEventDisableTiming) == cudaSuccess)
              && (cudaEventCreateWithFlags(&ev1, cudaEventDisableTiming) == cudaSuccess)
              && (cudaEventCreateWithFlags(&evj, cudaEventDisableTiming) == cudaSuccess);
        }
    };
    static Res res;   // constructed before main()
}

// ---------------------------------------------------------------------------
// Kernel 1 (per half): 512 threads = 16 warps = 16 tokens/block, 512 blocks.
// Weights folded into smem per block (L2-hit). 1 token per warp:
// 1 streaming LDG.128 + 4 LDS.128 per 512B of rep. Proven form (R3).
// ---------------------------------------------------------------------------
__global__ void __launch_bounds__(512)
logits_kernel(const float* __restrict__ rep,
              const int*   __restrict__ mask,
              const float* __restrict__ Ws,  const float* __restrict__ bs,
              const float* __restrict__ We,  const float* __restrict__ be,
              const float* __restrict__ Wm,  const float* __restrict__ bm,
              int tbase)
{
    __shared__ float s_wds[HH];   // Ws[:,1]-Ws[:,0]
    __shared__ float s_wss[HH];   // Wm0*Ws[:,0]+Wm1*Ws[:,1]
    __shared__ float s_wde[HH];   // We[:,1]-We[:,0]
    __shared__ float s_wse[HH];   // Wm2*We[:,0]+Wm3*We[:,1]
    __shared__ float s_bias[4];

    const int tid = threadIdx.x;
    {
        const float wm0 = Wm[0], wm1 = Wm[1], wm2 = Wm[2], wm3 = Wm[3];
        #pragma unroll
        for (int p = 0; p < HH / 512; p++) {
            int h = p * 512 + tid;
            float a0 = Ws[2 * h], a1 = Ws[2 * h + 1];
            float c0 = We[2 * h], c1 = We[2 * h + 1];
            s_wds[h] = a1 - a0;
            s_wss[h] = wm0 * a0 + wm1 * a1;
            s_wde[h] = c1 - c0;
            s_wse[h] = wm2 * c0 + wm3 * c1;
        }
        if (tid == 0) {
            s_bias[0] = bs[1] - bs[0];
            s_bias[1] = wm0 * bs[0] + wm1 * bs[1];
            s_bias[2] = be[1] - be[0];
            s_bias[3] = wm2 * be[0] + wm3 * be[1] + bm[0];
        }
    }
    __syncthreads();

    const int t    = tbase + blockIdx.x * 16 + (tid >> 5);   // token id
    const int lane = tid & 31;

    const float4* r4  = reinterpret_cast<const float4*>(rep + (size_t)t * HH);
    const float4* wds = reinterpret_cast<const float4*>(s_wds);
    const float4* wss = reinterpret_cast<const float4*>(s_wss);
    const float4* wde = reinterpret_cast<const float4*>(s_wde);
    const float4* wse = reinterpret_cast<const float4*>(s_wse);

    float ds = 0.f, sv = 0.f, de = 0.f, se = 0.f;
    #pragma unroll
    for (int k = 0; k < HH / 128; k++) {
        int idx = k * 32 + lane;
        float4 r = __ldcs(&r4[idx]);         // streaming: rep is read-once
        float4 a = wds[idx];
        float4 b = wss[idx];
        float4 c = wde[idx];
        float4 d = wse[idx];
        ds += r.x*a.x + r.y*a.y + r.z*a.z + r.w*a.w;
        sv += r.x*b.x + r.y*b.y + r.z*b.z + r.w*b.w;
        de += r.x*c.x + r.y*c.y + r.z*c.z + r.w*c.w;
        se += r.x*d.x + r.y*d.y + r.z*d.z + r.w*d.w;
    }
    #pragma unroll
    for (int off = 16; off; off >>= 1) {
        ds += __shfl_xor_sync(0xffffffffu, ds, off);
        sv += __shfl_xor_sync(0xffffffffu, sv, off);
        de += __shfl_xor_sync(0xffffffffu, de, off);
        se += __shfl_xor_sync(0xffffffffu, se, off);
    }
    if (lane == 0) {
        int m  = (mask[t] != 0);
        int sc = m && ((ds + s_bias[0]) >= 0.f);   // s0 <= s1
        int ec = m && ((de + s_bias[2]) >= 0.f);   // e0 <= e1
        g_ss[t] = sv + s_bias[1];
        g_se[t] = se + s_bias[3];
        g_fl[t] = sc | (ec << 1);
    }
}

// ---------------------------------------------------------------------------
// Kernel 2 (per half): grid (SS, HB); one block per (batch,row); 512 threads
// x float4 = 2048 cols. 8192 blocks per half -> full-size store efficiency.
// ---------------------------------------------------------------------------
__global__ void __launch_bounds__(512)
pair_kernel(float* __restrict__ out_valid,
            float* __restrict__ out_masked,
            int b0)
{
    const int i = blockIdx.x;
    const int b = b0 + blockIdx.y;
    const int t = b * SS + i;

    const float ss = g_ss[t];
    const bool  sc = (g_fl[t] & 1);

    const size_t rowoff = ((size_t)b * SS + i) * SS;
    float4* ov = reinterpret_cast<float4*>(out_valid  + rowoff);
    float4* om = reinterpret_cast<float4*>(out_masked + rowoff);

    const int j4 = threadIdx.x;        // one float4 (4 j's) per thread
    const int j0 = j4 * 4;

    float4 v, m;
    if (!sc || (j0 + 3) < i) {
        v = make_float4(0.f, 0.f, 0.f, 0.f);
        m = v;
    } else {
        const float4 se4 = reinterpret_cast<const float4*>(g_se + b * SS)[j4];
        const int4   fl4 = reinterpret_cast<const int4*>(g_fl + b * SS)[j4];

        float ps; bool val;
        ps = ss + se4.x; val = (fl4.x & 2) && (i <= j0 + 0) && (ps > 0.f);
        v.x = val ? 1.f : 0.f; m.x = val ? ps : 0.f;
        ps = ss + se4.y; val = (fl4.y & 2) && (i <= j0 + 1) && (ps > 0.f);
        v.y = val ? 1.f : 0.f; m.y = val ? ps : 0.f;
        ps = ss + se4.z; val = (fl4.z & 2) && (i <= j0 + 2) && (ps > 0.f);
        v.z = val ? 1.f : 0.f; m.z = val ? ps : 0.f;
        ps = ss + se4.w; val = (fl4.w & 2) && (i <= j0 + 3) && (ps > 0.f);
        v.w = val ? 1.f : 0.f; m.w = val ? ps : 0.f;
    }
    __stcs(ov + j4, v);
    __stcs(om + j4, m);
}

extern "C" void kernel_launch(void* const* d_in, const int* in_sizes, int n_in,
                              void* d_out, int out_size)
{
    const float* rep  = (const float*)d_in[0];
    const int*   mask = (const int*)  d_in[1];
    const float* Ws   = (const float*)d_in[2];
    const float* bs   = (const float*)d_in[3];
    const float* We   = (const float*)d_in[4];
    const float* be   = (const float*)d_in[5];
    const float* Wm   = (const float*)d_in[6];
    const float* bm   = (const float*)d_in[7];

    float* out = (float*)d_out;
    const size_t half = (size_t)BB * SS * SS;   // valid first, masked second

    const int blksL = (HB * SS) / 16;           // 512 logits blocks per half
    const dim3 gP(SS, HB);                      // 8192 pair blocks per half

    if (pipe::res.ok) {
        // Fork: pair_A (side stream) overlaps logits_B (default stream).
        logits_kernel<<<blksL, 512>>>(rep, mask, Ws, bs, We, be, Wm, bm, 0);
        cudaEventRecord(pipe::res.ev0, 0);
        logits_kernel<<<blksL, 512>>>(rep, mask, Ws, bs, We, be, Wm, bm, HB * SS);
        cudaEventRecord(pipe::res.ev1, 0);

        cudaStreamWaitEvent(pipe::res.s2, pipe::res.ev0, 0);
        pair_kernel<<<gP, 512, 0, pipe::res.s2>>>(out, out + half, 0);
        cudaStreamWaitEvent(pipe::res.s2, pipe::res.ev1, 0);
        pair_kernel<<<gP, 512, 0, pipe::res.s2>>>(out, out + half, HB);

        cudaEventRecord(pipe::res.evj, pipe::res.s2);
        cudaStreamWaitEvent(0, pipe::res.evj, 0);
    } else {
        // Fallback: sequential on default stream (proven 58us structure).
        logits_kernel<<<blksL, 512>>>(rep, mask, Ws, bs, We, be, Wm, bm, 0);
        logits_kernel<<<blksL, 512>>>(rep, mask, Ws, bs, We, be, Wm, bm, HB * SS);
        pair_kernel<<<gP, 512>>>(out, out + half, 0);
        pair_kernel<<<gP, 512>>>(out, out + half, HB);
    }
}